// round 5
// baseline (speedup 1.0000x reference)
#include <cuda_runtime.h>
#include <cstdint>

// Problem constants
#define BB 8
#define NN 256
#define FF 64      // OUT_F == OUT_E
#define KE 32      // IN_E
#define KN 64      // IN_F
#define NODE_OUT_ELEMS (BB * NN * FF)

typedef unsigned long long u64;

// ---------------- packed f32x2 helpers ----------------
__device__ __forceinline__ u64 fadd2(u64 a, u64 b) {
    u64 d; asm("add.rn.f32x2 %0, %1, %2;" : "=l"(d) : "l"(a), "l"(b)); return d;
}
__device__ __forceinline__ u64 pack2(float lo, float hi) {
    u64 r; asm("mov.b64 %0, {%1, %2};" : "=l"(r) : "f"(lo), "f"(hi)); return r;
}
__device__ __forceinline__ float2 unpack2(u64 v) {
    float2 r; asm("mov.b64 {%0, %1}, %2;" : "=f"(r.x), "=f"(r.y) : "l"(v)); return r;
}
__device__ __forceinline__ uint32_t tf32_rna(float v) {
    uint32_t h; asm("cvt.rna.tf32.f32 %0, %1;" : "=r"(h) : "f"(v));
    return h;
}

// ---------------- cp.async helpers ----------------
__device__ __forceinline__ uint32_t smem_u32(const void* p) {
    uint32_t a;
    asm("{ .reg .u64 t; cvta.to.shared.u64 t, %1; cvt.u32.u64 %0, t; }" : "=r"(a) : "l"(p));
    return a;
}
__device__ __forceinline__ void cpa16(uint32_t saddr, const void* g) {
    asm volatile("cp.async.cg.shared.global [%0], [%1], 16;" :: "r"(saddr), "l"(g));
}
__device__ __forceinline__ void cpa_commit_wait() {
    asm volatile("cp.async.commit_group;");
    asm volatile("cp.async.wait_group 0;");
}

// ---------------- tf32 mma.sync ----------------
__device__ __forceinline__ void mma_tf32(float* c, const uint32_t* a, const uint32_t* b) {
    asm volatile(
        "mma.sync.aligned.m16n8k8.row.col.f32.tf32.tf32.f32 "
        "{%0,%1,%2,%3}, {%4,%5,%6,%7}, {%8,%9}, {%0,%1,%2,%3};"
        : "+f"(c[0]), "+f"(c[1]), "+f"(c[2]), "+f"(c[3])
        : "r"(a[0]), "r"(a[1]), "r"(a[2]), "r"(a[3]), "r"(b[0]), "r"(b[1]));
}

// ---------------- scratch ----------------
__device__ float  g_nodex[BB * NN * FF];     // node_x [b][m][f]
__device__ float  g_rsx[BB * NN * FF];       // relu(node_sx)
__device__ float2 g_part[2 * BB * NN * 32];  // per-half partial agg sums
// B fragment packs (tf32 hi / lo): layout ((nt*4+ks)*32+lane)*2 + {b0,b1}
__device__ uint32_t g_Bph[8 * 4 * 32 * 2];   // 8 KB
__device__ uint32_t g_Bpl[8 * 4 * 32 * 2];   // 8 KB

// ============================================================
// Kernel 1: node projections + (CTA 0) B fragment pack prep
// ============================================================
__global__ void __launch_bounds__(256) node_proj_kernel(
    const float* __restrict__ emb_node,
    const float* __restrict__ W_node, const float* __restrict__ b_node,
    const float* __restrict__ W_nodes, const float* __restrict__ b_nodes,
    const float* __restrict__ W_edge)
{
    __shared__ float wsm0[KN * FF];
    __shared__ float wsm1[KN * FF];
    __shared__ float rsm[8 * KN];

    const int tid = threadIdx.x;
    const int row0 = blockIdx.x * 8;

    if (blockIdx.x == 0) {
        // B fragment packs: b0 = W[ks*8+lane%4][nt*8+lane/4], b1 = W[k+4][n]
        #pragma unroll
        for (int i = 0; i < 8; i++) {
            int idx = tid + i * 256;              // 0..2047
            int h0   = idx & 1;
            int lane = (idx >> 1) & 31;
            int ks   = (idx >> 6) & 3;
            int nt   = idx >> 8;
            int k = ks * 8 + (lane & 3) + 4 * h0;
            int f = nt * 8 + (lane >> 2);
            float v = W_edge[k * FF + f];
            uint32_t hi = tf32_rna(v);
            float lo = v - __uint_as_float(hi);
            g_Bph[idx] = hi;
            g_Bpl[idx] = tf32_rna(lo);
        }
    }

    {
        const float4* w0 = (const float4*)W_node;
        const float4* w1 = (const float4*)W_nodes;
        #pragma unroll
        for (int i = tid; i < KN * FF / 4; i += 256) {
            ((float4*)wsm0)[i] = w0[i];
            ((float4*)wsm1)[i] = w1[i];
        }
        if (tid < 128)
            ((float4*)rsm)[tid] = ((const float4*)(emb_node + (size_t)row0 * KN))[tid];
    }
    __syncthreads();

    const int rl = tid >> 6;
    const int f  = tid & 63;

    float nx0 = b_node[f], sx0 = b_nodes[f];
    float nx1 = nx0,       sx1 = sx0;
    #pragma unroll
    for (int k = 0; k < KN; k++) {
        float a0 = rsm[rl * KN + k];
        float a1 = rsm[(rl + 4) * KN + k];
        float w0 = wsm0[k * FF + f];
        float w1 = wsm1[k * FF + f];
        nx0 = fmaf(a0, w0, nx0);  sx0 = fmaf(a0, w1, sx0);
        nx1 = fmaf(a1, w0, nx1);  sx1 = fmaf(a1, w1, sx1);
    }

    const int ga = row0 + rl;
    const int gb = row0 + rl + 4;
    g_nodex[(size_t)ga * FF + f] = nx0;
    g_nodex[(size_t)gb * FF + f] = nx1;
    g_rsx[(size_t)ga * FF + f] = fmaxf(sx0, 0.0f);
    g_rsx[(size_t)gb * FF + f] = fmaxf(sx1, 0.0f);
}

// ============================================================
// Kernel 2: per (b,n,half) CTA — 128 m x 64 f x 32 k via tf32 mma.sync (3xTF32)
//   8 warps; warp w owns m-rows [w*16, w*16+16)
// ============================================================
// dynamic smem layout
#define OFF_BES  0          // 256 B bias
#define OFF_ASM  256        // 512 B A slice (128 floats)
#define OFF_RED  768        // 2048 B cross-warp reduce (8 warps x 32 float2)
#define OFF_RAW  4096       // 18432 B raw A-slice, rows padded to 36 floats
#define OFF_AHI  22528      // 16384 B packed A hi fragments
#define OFF_ALO  38912      // 16384 B packed A lo fragments
#define OFF_BHI  55296      // 8192 B
#define OFF_BLO  63488      // 8192 B
#define EDGE_SMEM_TOTAL 71680

__global__ void __launch_bounds__(256, 3) edge_kernel(
    const float* __restrict__ A,
    const float* __restrict__ emb_edge,
    const float* __restrict__ b_edge,
    float* __restrict__ out)
{
    extern __shared__ char smem[];
    const uint32_t sb = smem_u32(smem);
    const int tid  = threadIdx.x;
    const int w    = tid >> 5;
    const int lane = tid & 31;
    const int g2   = blockIdx.x;          // (b*256+n)*2 + half
    const int g    = g2 >> 1;
    const int half = g2 & 1;
    const int b    = g >> 8;

    // ---- stage via cp.async ----
    {
        // raw A-slice: 128 rows x 32 floats -> padded 36-float rows
        const float4* esrc =
            (const float4*)(emb_edge + ((size_t)g * NN + half * 128) * KE);
        #pragma unroll
        for (int i = 0; i < 4; i++) {
            int c = tid + i * 256;            // 0..1023 16B chunks
            int row = c >> 3, c8 = c & 7;
            cpa16(sb + OFF_RAW + row * 144 + c8 * 16, esrc + c);
        }
        // B packs
        #pragma unroll
        for (int i = 0; i < 2; i++) {
            int c = tid + i * 256;            // 512 chunks
            cpa16(sb + OFF_BHI + c * 16, ((const float4*)g_Bph) + c);
            cpa16(sb + OFF_BLO + c * 16, ((const float4*)g_Bpl) + c);
        }
        if (tid < 32)
            cpa16(sb + OFF_ASM + tid * 16,
                  ((const float4*)(A + (size_t)g * NN + half * 128)) + tid);
        if (tid < 16)
            cpa16(sb + OFF_BES + tid * 16, ((const float4*)b_edge) + tid);
        cpa_commit_wait();
    }
    __syncthreads();

    // ---- transform: raw -> packed tf32 hi/lo A fragments ----
    {
        const float* raw = (const float*)(smem + OFF_RAW);
        uint4* ahi = (uint4*)(smem + OFF_AHI);
        uint4* alo = (uint4*)(smem + OFF_ALO);
        #pragma unroll
        for (int i = 0; i < 4; i++) {
            int s = tid + i * 256;            // 0..1023 fragment slots
            int l = s & 31;
            int q = s >> 5;                   // (wslot*4 + ks)
            int r0 = (q >> 2) * 16 + (l >> 2);
            int c0 = (q & 3) * 8 + (l & 3);
            float v0 = raw[r0 * 36 + c0];
            float v1 = raw[(r0 + 8) * 36 + c0];
            float v2 = raw[r0 * 36 + c0 + 4];
            float v3 = raw[(r0 + 8) * 36 + c0 + 4];
            uint4 h;
            h.x = tf32_rna(v0); h.y = tf32_rna(v1);
            h.z = tf32_rna(v2); h.w = tf32_rna(v3);
            uint4 lo;
            lo.x = tf32_rna(v0 - __uint_as_float(h.x));
            lo.y = tf32_rna(v1 - __uint_as_float(h.y));
            lo.z = tf32_rna(v2 - __uint_as_float(h.z));
            lo.w = tf32_rna(v3 - __uint_as_float(h.w));
            ahi[s] = h;
            alo[s] = lo;
        }
    }
    __syncthreads();

    // ---- GEMM: 8 n-tiles x 4 k-steps x 3 passes per warp ----
    float acc[8][4];
    #pragma unroll
    for (int nt = 0; nt < 8; nt++)
        #pragma unroll
        for (int j = 0; j < 4; j++) acc[nt][j] = 0.0f;

    {
        const uint4* ahi = (const uint4*)(smem + OFF_AHI);
        const uint4* alo = (const uint4*)(smem + OFF_ALO);
        const uint2* bhi = (const uint2*)(smem + OFF_BHI);
        const uint2* blo = (const uint2*)(smem + OFF_BLO);
        #pragma unroll
        for (int ks = 0; ks < 4; ks++) {
            const int as = (w * 4 + ks) * 32 + lane;
            uint4 ah4 = ahi[as];
            uint4 al4 = alo[as];
            uint32_t ah[4] = {ah4.x, ah4.y, ah4.z, ah4.w};
            uint32_t al[4] = {al4.x, al4.y, al4.z, al4.w};
            #pragma unroll
            for (int nt = 0; nt < 8; nt++) {
                const int bs = (nt * 4 + ks) * 32 + lane;
                uint2 bh2 = bhi[bs];
                uint2 bl2 = blo[bs];
                uint32_t bh[2] = {bh2.x, bh2.y};
                uint32_t bl[2] = {bl2.x, bl2.y};
                mma_tf32(acc[nt], ah, bh);
                mma_tf32(acc[nt], ah, bl);
                mma_tf32(acc[nt], al, bh);
            }
        }
    }

    // ---- epilogue ----
    // thread's rows: m0 = half*128 + w*16 + lane/4, m1 = m0 + 8
    // thread's cols: f0 = nt*8 + 2*(lane%4), f0+1
    const int ml0 = w * 16 + (lane >> 2);
    const int m0  = half * 128 + ml0;
    const int m1  = m0 + 8;
    const float Am0 = ((const float*)(smem + OFF_ASM))[ml0];
    const float Am1 = ((const float*)(smem + OFF_ASM))[ml0 + 8];
    const float* bes = (const float*)(smem + OFF_BES);
    float* eout = out + NODE_OUT_ELEMS + (size_t)g * (NN * FF);
    const float* nxb = g_nodex + (size_t)b * (NN * FF);

    u64 part[8];
    #pragma unroll
    for (int nt = 0; nt < 8; nt++) {
        const int f0 = nt * 8 + 2 * (lane & 3);
        float ex0 = acc[nt][0] + bes[f0];
        float ex1 = acc[nt][1] + bes[f0 + 1];
        float ex2 = acc[nt][2] + bes[f0];
        float ex3 = acc[nt][3] + bes[f0 + 1];

        *(float2*)&eout[(size_t)m0 * FF + f0] =
            make_float2(fmaxf(ex0, 0.f), fmaxf(ex1, 0.f));
        *(float2*)&eout[(size_t)m1 * FF + f0] =
            make_float2(fmaxf(ex2, 0.f), fmaxf(ex3, 0.f));

        float2 nx0 = *(const float2*)&nxb[(size_t)m0 * FF + f0];
        float2 nx1 = *(const float2*)&nxb[(size_t)m1 * FF + f0];
        float px = fmaf(Am0 * nx0.x, ex0, Am1 * nx1.x * ex2);
        float py = fmaf(Am0 * nx0.y, ex1, Am1 * nx1.y * ex3);
        part[nt] = pack2(px, py);
    }

    // reduce over lane/4 groups (8 rows): xor 4, 8, 16
    #pragma unroll
    for (int d = 4; d <= 16; d <<= 1) {
        #pragma unroll
        for (int nt = 0; nt < 8; nt++)
            part[nt] = fadd2(part[nt], __shfl_xor_sync(0xffffffffu, part[nt], d));
    }
    if (lane < 4) {
        float2* red = (float2*)(smem + OFF_RED);
        #pragma unroll
        for (int nt = 0; nt < 8; nt++)
            red[w * 32 + nt * 4 + lane] = unpack2(part[nt]);
    }
    __syncthreads();

    if (tid < 32) {
        const float2* red = (const float2*)(smem + OFF_RED);
        float2 s = red[tid];
        #pragma unroll
        for (int q = 1; q < 8; q++) {
            float2 v = red[q * 32 + tid];
            s.x += v.x; s.y += v.y;
        }
        g_part[(size_t)g2 * 32 + tid] = s;
    }
}

// ============================================================
// Kernel 3: combine halves -> node_out = relu(p0+p1) + rsx
// ============================================================
__global__ void __launch_bounds__(256) finish_kernel(float* __restrict__ out)
{
    const int idx = blockIdx.x * 256 + threadIdx.x;   // 0..65535
    const int g  = idx >> 5;
    const int fp = idx & 31;
    float2 a = g_part[(size_t)(2 * g) * 32 + fp];
    float2 b = g_part[(size_t)(2 * g + 1) * 32 + fp];
    float2 r = *(const float2*)&g_rsx[(size_t)g * FF + 2 * fp];
    float2 o;
    o.x = fmaxf(a.x + b.x, 0.0f) + r.x;
    o.y = fmaxf(a.y + b.y, 0.0f) + r.y;
    *(float2*)&out[(size_t)g * FF + 2 * fp] = o;
}

// ============================================================
// launch
// ============================================================
extern "C" void kernel_launch(void* const* d_in, const int* in_sizes, int n_in,
                              void* d_out, int out_size)
{
    const float* A        = (const float*)d_in[0];
    const float* emb_node = (const float*)d_in[1];
    const float* emb_edge = (const float*)d_in[2];
    const float* W_node   = (const float*)d_in[3];
    const float* b_node   = (const float*)d_in[4];
    const float* W_nodes  = (const float*)d_in[5];
    const float* b_nodes  = (const float*)d_in[6];
    const float* W_edge   = (const float*)d_in[7];
    const float* b_edge   = (const float*)d_in[8];
    float* out = (float*)d_out;

    static int attr_set = 0;
    if (!attr_set) {
        cudaFuncSetAttribute(edge_kernel,
                             cudaFuncAttributeMaxDynamicSharedMemorySize, EDGE_SMEM_TOTAL);
        attr_set = 1;
    }

    node_proj_kernel<<<256, 256>>>(emb_node, W_node, b_node, W_nodes, b_nodes, W_edge);
    edge_kernel<<<2 * BB * NN, 256, EDGE_SMEM_TOTAL>>>(A, emb_edge, b_edge, out);
    finish_kernel<<<256, 256>>>(out);
}

// round 7
// speedup vs baseline: 1.2902x; 1.2902x over previous
#include <cuda_runtime.h>
#include <cstdint>

// Problem constants
#define BB 8
#define NN 256
#define FF 64      // OUT_F == OUT_E
#define KE 32      // IN_E
#define KN 64      // IN_F
#define NODE_OUT_ELEMS (BB * NN * FF)

typedef unsigned long long u64;

// ---------------- packed f32x2 helpers ----------------
__device__ __forceinline__ u64 ffma2(u64 a, u64 b, u64 c) {
    u64 d; asm("fma.rn.f32x2 %0, %1, %2, %3;" : "=l"(d) : "l"(a), "l"(b), "l"(c)); return d;
}
__device__ __forceinline__ u64 fmul2(u64 a, u64 b) {
    u64 d; asm("mul.rn.f32x2 %0, %1, %2;" : "=l"(d) : "l"(a), "l"(b)); return d;
}
__device__ __forceinline__ u64 fadd2(u64 a, u64 b) {
    u64 d; asm("add.rn.f32x2 %0, %1, %2;" : "=l"(d) : "l"(a), "l"(b)); return d;
}
__device__ __forceinline__ u64 pack2(float lo, float hi) {
    u64 r; asm("mov.b64 %0, {%1, %2};" : "=l"(r) : "f"(lo), "f"(hi)); return r;
}
__device__ __forceinline__ float2 unpack2(u64 v) {
    float2 r; asm("mov.b64 {%0, %1}, %2;" : "=f"(r.x), "=f"(r.y) : "l"(v)); return r;
}
__device__ __forceinline__ uint32_t tf32_rna(float v) {
    uint32_t h; asm("cvt.rna.tf32.f32 %0, %1;" : "=r"(h) : "f"(v));
    return h;
}

// ---------------- cp.async helpers ----------------
__device__ __forceinline__ uint32_t smem_u32(const void* p) {
    uint32_t a;
    asm("{ .reg .u64 t; cvta.to.shared.u64 t, %1; cvt.u32.u64 %0, t; }" : "=r"(a) : "l"(p));
    return a;
}
__device__ __forceinline__ void cpa16(uint32_t saddr, const void* g) {
    asm volatile("cp.async.cg.shared.global [%0], [%1], 16;" :: "r"(saddr), "l"(g));
}
__device__ __forceinline__ void cpa_commit_wait() {
    asm volatile("cp.async.commit_group;");
    asm volatile("cp.async.wait_group 0;");
}

// ---------------- tf32 mma.sync (layout verified in R5) ----------------
__device__ __forceinline__ void mma_tf32(float* c, const uint32_t* a, const uint32_t* b) {
    asm volatile(
        "mma.sync.aligned.m16n8k8.row.col.f32.tf32.tf32.f32 "
        "{%0,%1,%2,%3}, {%4,%5,%6,%7}, {%8,%9}, {%0,%1,%2,%3};"
        : "+f"(c[0]), "+f"(c[1]), "+f"(c[2]), "+f"(c[3])
        : "r"(a[0]), "r"(a[1]), "r"(a[2]), "r"(a[3]), "r"(b[0]), "r"(b[1]));
}

// ---------------- scratch ----------------
__device__ float g_rsx[BB * NN * FF];        // relu(node_sx)
// node_x pre-scattered into epilogue fragment layout:
// float2 index: (((b*8 + w)*4 + rs)*8 + nt)*32 + lane ; pair (f0, f0+1), f0 = nt*8+2*(lane&3)
// row m = 32w + 8rs + (lane>>2)
__device__ float g_nxF[BB * NN * FF];        // 512 KB
// interleaved B fragment packs: uint4 {bh0, bh1, bl0, bl1} at [(nt*4+ks)*32 + lane]
__device__ uint4 g_Bp[8 * 4 * 32];           // 16 KB

// ============================================================
// Kernel 1: node projections (+ CTA 0: B pack prep)
// ============================================================
__global__ void __launch_bounds__(256) node_proj_kernel(
    const float* __restrict__ emb_node,
    const float* __restrict__ W_node, const float* __restrict__ b_node,
    const float* __restrict__ W_nodes, const float* __restrict__ b_nodes,
    const float* __restrict__ W_edge)
{
    __shared__ float wsm0[KN * FF];
    __shared__ float wsm1[KN * FF];
    __shared__ float rsm[8 * KN];

    const int tid = threadIdx.x;
    const int row0 = blockIdx.x * 8;

    if (blockIdx.x == 0) {
        // B fragment packs (interleaved hi/lo)
        #pragma unroll
        for (int i = 0; i < 4; i++) {
            int idx = tid + i * 256;              // 0..1023
            int lane = idx & 31;
            int ks   = (idx >> 5) & 3;
            int nt   = idx >> 7;
            int k0 = ks * 8 + (lane & 3);
            int f  = nt * 8 + (lane >> 2);
            float v0 = W_edge[k0 * FF + f];
            float v1 = W_edge[(k0 + 4) * FF + f];
            uint32_t h0 = tf32_rna(v0), h1 = tf32_rna(v1);
            uint4 p;
            p.x = h0; p.y = h1;
            p.z = tf32_rna(v0 - __uint_as_float(h0));
            p.w = tf32_rna(v1 - __uint_as_float(h1));
            g_Bp[idx] = p;
        }
    }

    {
        const float4* w0 = (const float4*)W_node;
        const float4* w1 = (const float4*)W_nodes;
        #pragma unroll
        for (int i = tid; i < KN * FF / 4; i += 256) {
            ((float4*)wsm0)[i] = w0[i];
            ((float4*)wsm1)[i] = w1[i];
        }
        if (tid < 128)
            ((float4*)rsm)[tid] = ((const float4*)(emb_node + (size_t)row0 * KN))[tid];
    }
    __syncthreads();

    const int rl = tid >> 6;
    const int f  = tid & 63;

    float nx0 = b_node[f], sx0 = b_nodes[f];
    float nx1 = nx0,       sx1 = sx0;
    #pragma unroll
    for (int k = 0; k < KN; k++) {
        float a0 = rsm[rl * KN + k];
        float a1 = rsm[(rl + 4) * KN + k];
        float w0 = wsm0[k * FF + f];
        float w1 = wsm1[k * FF + f];
        nx0 = fmaf(a0, w0, nx0);  sx0 = fmaf(a0, w1, sx0);
        nx1 = fmaf(a1, w0, nx1);  sx1 = fmaf(a1, w1, sx1);
    }

    // scatter node_x into fragment layout
    const int nt = f >> 3;
    const int cc = (f >> 1) & 3;
    const int j  = f & 1;
    {
        const int ga = row0 + rl;
        const int bbv = ga >> 8, m = ga & 255;
        const int w1i = m >> 5, rs = (m >> 3) & 3, lp = ((m & 7) << 2) | cc;
        g_nxF[(size_t)(((((bbv * 8 + w1i) * 4 + rs) * 8 + nt) * 32 + lp) * 2 + j)] = nx0;
        g_rsx[(size_t)ga * FF + f] = fmaxf(sx0, 0.0f);
    }
    {
        const int gb = row0 + rl + 4;
        const int bbv = gb >> 8, m = gb & 255;
        const int w1i = m >> 5, rs = (m >> 3) & 3, lp = ((m & 7) << 2) | cc;
        g_nxF[(size_t)(((((bbv * 8 + w1i) * 4 + rs) * 8 + nt) * 32 + lp) * 2 + j)] = nx1;
        g_rsx[(size_t)gb * FF + f] = fmaxf(sx1, 0.0f);
    }
}

// ============================================================
// Kernel 2: per (b,n) CTA — 256 m x 64 f x 32 k via tf32 mma.sync (3xTF32)
//   8 warps; warp w owns m-tiles {2w, 2w+1} (rows 32w..32w+32), all 8 n-tiles
// ============================================================
#define OFF_BES  0          // 256 B bias
#define OFF_ASM  256        // 1024 B A row (256 floats)
#define OFF_RED  1280       // 2048 B (8 warps x 32 float2)
#define OFF_RAW  3328       // 36864 B raw A, rows padded to 36 floats
#define OFF_B    40192      // 16384 B interleaved B frag packs
#define EDGE_SMEM_TOTAL 56576

__global__ void __launch_bounds__(256, 2) edge_kernel(
    const float* __restrict__ A,
    const float* __restrict__ emb_edge,
    const float* __restrict__ b_edge,
    float* __restrict__ out)
{
    extern __shared__ char smem[];
    const uint32_t sb = smem_u32(smem);
    const int tid  = threadIdx.x;
    const int w    = tid >> 5;
    const int lane = tid & 31;
    const int g    = blockIdx.x;          // b*256 + n
    const int b    = g >> 8;

    // ---- stage via cp.async ----
    {
        const float4* esrc = (const float4*)(emb_edge + (size_t)g * (NN * KE));
        #pragma unroll
        for (int i = 0; i < 8; i++) {
            int c = tid + i * 256;            // 0..2047 16B chunks (256 rows x 8)
            int row = c >> 3, c8 = c & 7;
            cpa16(sb + OFF_RAW + row * 144 + c8 * 16, esrc + c);
        }
        #pragma unroll
        for (int i = 0; i < 4; i++) {
            int c = tid + i * 256;            // 1024 chunks of B pack
            cpa16(sb + OFF_B + c * 16, ((const uint4*)g_Bp) + c);
        }
        if (tid < 64)
            cpa16(sb + OFF_ASM + tid * 16, ((const float4*)(A + (size_t)g * NN)) + tid);
        if (tid < 16)
            cpa16(sb + OFF_BES + tid * 16, ((const float4*)b_edge) + tid);
        cpa_commit_wait();
    }
    __syncthreads();

    const float* raw = (const float*)(smem + OFF_RAW);
    const uint4* Bsm = (const uint4*)(smem + OFF_B);

    // ---- GEMM: 2 m-tiles x 8 n-tiles x 4 k-steps x 3 passes ----
    float acc[2][8][4];
    #pragma unroll
    for (int t2 = 0; t2 < 2; t2++)
        #pragma unroll
        for (int nt = 0; nt < 8; nt++)
            #pragma unroll
            for (int j = 0; j < 4; j++) acc[t2][nt][j] = 0.0f;

    #pragma unroll
    for (int ks = 0; ks < 4; ks++) {
        uint32_t ah[2][4], al[2][4];
        #pragma unroll
        for (int t2 = 0; t2 < 2; t2++) {
            const int r0 = (2 * w + t2) * 16 + (lane >> 2);
            const int c0 = ks * 8 + (lane & 3);
            float v0 = raw[r0 * 36 + c0];
            float v1 = raw[(r0 + 8) * 36 + c0];
            float v2 = raw[r0 * 36 + c0 + 4];
            float v3 = raw[(r0 + 8) * 36 + c0 + 4];
            ah[t2][0] = tf32_rna(v0); ah[t2][1] = tf32_rna(v1);
            ah[t2][2] = tf32_rna(v2); ah[t2][3] = tf32_rna(v3);
            al[t2][0] = tf32_rna(v0 - __uint_as_float(ah[t2][0]));
            al[t2][1] = tf32_rna(v1 - __uint_as_float(ah[t2][1]));
            al[t2][2] = tf32_rna(v2 - __uint_as_float(ah[t2][2]));
            al[t2][3] = tf32_rna(v3 - __uint_as_float(ah[t2][3]));
        }
        #pragma unroll
        for (int nt = 0; nt < 8; nt++) {
            uint4 Bv = Bsm[(nt * 4 + ks) * 32 + lane];
            uint32_t bh[2] = {Bv.x, Bv.y};
            uint32_t bl[2] = {Bv.z, Bv.w};
            #pragma unroll
            for (int t2 = 0; t2 < 2; t2++) {
                mma_tf32(acc[t2][nt], ah[t2], bh);
                mma_tf32(acc[t2][nt], al[t2], bh);
                mma_tf32(acc[t2][nt], ah[t2], bl);
            }
        }
    }

    // ---- epilogue ----
    const float* Asmf = (const float*)(smem + OFF_ASM);
    const float* bes  = (const float*)(smem + OFF_BES);
    float* eout = out + NODE_OUT_ELEMS + (size_t)g * (NN * FF);
    const float2* nxw = ((const float2*)g_nxF) + ((size_t)(b * 8 + w)) * 1024;

    float2 bf[8];
    #pragma unroll
    for (int nt = 0; nt < 8; nt++)
        bf[nt] = *(const float2*)&bes[nt * 8 + 2 * (lane & 3)];

    u64 part[8];
    #pragma unroll
    for (int nt = 0; nt < 8; nt++) part[nt] = 0ull;

    #pragma unroll
    for (int rs = 0; rs < 4; rs++) {
        const int m = 32 * w + 8 * rs + (lane >> 2);
        const float Am = Asmf[m];
        const u64 A2 = pack2(Am, Am);
        const int t2 = rs >> 1;
        const int hi = rs & 1;
        #pragma unroll
        for (int nt = 0; nt < 8; nt++) {
            float ex = acc[t2][nt][hi * 2 + 0] + bf[nt].x;
            float ey = acc[t2][nt][hi * 2 + 1] + bf[nt].y;
            *(float2*)&eout[(size_t)m * FF + nt * 8 + 2 * (lane & 3)] =
                make_float2(fmaxf(ex, 0.f), fmaxf(ey, 0.f));
            float2 nx = nxw[(rs * 8 + nt) * 32 + lane];
            part[nt] = ffma2(fmul2(A2, pack2(nx.x, nx.y)), pack2(ex, ey), part[nt]);
        }
    }

    // reduce over the 8 row-groups in the warp (flip bits of lane>>2)
    #pragma unroll
    for (int d = 4; d <= 16; d <<= 1) {
        #pragma unroll
        for (int nt = 0; nt < 8; nt++)
            part[nt] = fadd2(part[nt], __shfl_xor_sync(0xffffffffu, part[nt], d));
    }
    if (lane < 4) {
        float2* red = (float2*)(smem + OFF_RED);
        #pragma unroll
        for (int nt = 0; nt < 8; nt++)
            red[w * 32 + nt * 4 + lane] = unpack2(part[nt]);
    }
    __syncthreads();

    // combine 8 warps (8 m-chunks of 32 rows each) -> node_out
    if (tid < 32) {
        const float2* red = (const float2*)(smem + OFF_RED);
        float2 s = red[tid];
        #pragma unroll
        for (int q = 1; q < 8; q++) {
            float2 v = red[q * 32 + tid];
            s.x += v.x; s.y += v.y;
        }
        float2 rs2 = *(const float2*)&g_rsx[(size_t)g * FF + 2 * tid];
        float2 o;
        o.x = fmaxf(s.x, 0.0f) + rs2.x;
        o.y = fmaxf(s.y, 0.0f) + rs2.y;
        *(float2*)&out[(size_t)g * FF + 2 * tid] = o;
    }
}

// ============================================================
// launch
// ============================================================
extern "C" void kernel_launch(void* const* d_in, const int* in_sizes, int n_in,
                              void* d_out, int out_size)
{
    const float* A        = (const float*)d_in[0];
    const float* emb_node = (const float*)d_in[1];
    const float* emb_edge = (const float*)d_in[2];
    const float* W_node   = (const float*)d_in[3];
    const float* b_node   = (const float*)d_in[4];
    const float* W_nodes  = (const float*)d_in[5];
    const float* b_nodes  = (const float*)d_in[6];
    const float* W_edge   = (const float*)d_in[7];
    const float* b_edge   = (const float*)d_in[8];
    float* out = (float*)d_out;

    static int attr_set = 0;
    if (!attr_set) {
        cudaFuncSetAttribute(edge_kernel,
                             cudaFuncAttributeMaxDynamicSharedMemorySize, EDGE_SMEM_TOTAL);
        attr_set = 1;
    }

    node_proj_kernel<<<256, 256>>>(emb_node, W_node, b_node, W_nodes, b_nodes, W_edge);
    edge_kernel<<<BB * NN, 256, EDGE_SMEM_TOTAL>>>(A, emb_edge, b_edge, out);
}

// round 8
// speedup vs baseline: 1.3138x; 1.0183x over previous
#include <cuda_runtime.h>
#include <cstdint>

// Problem constants
#define BB 8
#define NN 256
#define FF 64      // OUT_F == OUT_E
#define KE 32      // IN_E
#define KN 64      // IN_F
#define NODE_OUT_ELEMS (BB * NN * FF)

typedef unsigned long long u64;

// ---------------- packed f32x2 helpers ----------------
__device__ __forceinline__ u64 ffma2(u64 a, u64 b, u64 c) {
    u64 d; asm("fma.rn.f32x2 %0, %1, %2, %3;" : "=l"(d) : "l"(a), "l"(b), "l"(c)); return d;
}
__device__ __forceinline__ u64 fmul2(u64 a, u64 b) {
    u64 d; asm("mul.rn.f32x2 %0, %1, %2;" : "=l"(d) : "l"(a), "l"(b)); return d;
}
__device__ __forceinline__ u64 fadd2(u64 a, u64 b) {
    u64 d; asm("add.rn.f32x2 %0, %1, %2;" : "=l"(d) : "l"(a), "l"(b)); return d;
}
__device__ __forceinline__ u64 pack2(float lo, float hi) {
    u64 r; asm("mov.b64 %0, {%1, %2};" : "=l"(r) : "f"(lo), "f"(hi)); return r;
}
__device__ __forceinline__ float2 unpack2(u64 v) {
    float2 r; asm("mov.b64 {%0, %1}, %2;" : "=f"(r.x), "=f"(r.y) : "l"(v)); return r;
}
__device__ __forceinline__ uint32_t tf32_rna(float v) {
    uint32_t h; asm("cvt.rna.tf32.f32 %0, %1;" : "=r"(h) : "f"(v));
    return h;
}

// ---------------- cp.async helpers ----------------
__device__ __forceinline__ uint32_t smem_u32(const void* p) {
    uint32_t a;
    asm("{ .reg .u64 t; cvta.to.shared.u64 t, %1; cvt.u32.u64 %0, t; }" : "=r"(a) : "l"(p));
    return a;
}
__device__ __forceinline__ void cpa16(uint32_t saddr, const void* g) {
    asm volatile("cp.async.cg.shared.global [%0], [%1], 16;" :: "r"(saddr), "l"(g));
}
__device__ __forceinline__ void cpa_commit_wait() {
    asm volatile("cp.async.commit_group;");
    asm volatile("cp.async.wait_group 0;");
}
__device__ __forceinline__ void stg_cs_f2(float* p, float x, float y) {
    asm volatile("st.global.cs.v2.f32 [%0], {%1, %2};" :: "l"(p), "f"(x), "f"(y));
}

// ---------------- tf32 mma.sync (layout verified in R5/R7) ----------------
__device__ __forceinline__ void mma_tf32(float* c, const uint32_t* a, const uint32_t* b) {
    asm volatile(
        "mma.sync.aligned.m16n8k8.row.col.f32.tf32.tf32.f32 "
        "{%0,%1,%2,%3}, {%4,%5,%6,%7}, {%8,%9}, {%0,%1,%2,%3};"
        : "+f"(c[0]), "+f"(c[1]), "+f"(c[2]), "+f"(c[3])
        : "r"(a[0]), "r"(a[1]), "r"(a[2]), "r"(a[3]), "r"(b[0]), "r"(b[1]));
}

// ---------------- scratch ----------------
__device__ float g_rsx[BB * NN * FF];        // relu(node_sx)
// node_x pre-scattered into epilogue fragment layout:
// float2 index: ((((b*2+half)*8 + w)*2 + rs)*8 + nt)*32 + lane
// row m = half*128 + w*16 + rs*8 + (lane>>2); pair f = nt*8 + 2*(lane&3) + {0,1}
__device__ float  g_nxF[BB * NN * FF];       // 512 KB
__device__ float2 g_part[2 * BB * NN * 32];  // per-half partial agg sums
// interleaved B fragment packs: uint4 {bh0, bh1, bl0, bl1} at [(nt*4+ks)*32 + lane]
__device__ uint4 g_Bp[8 * 4 * 32];           // 16 KB

// ============================================================
// Kernel 1: node projections (+ CTA 0: B pack prep)
// ============================================================
__global__ void __launch_bounds__(256) node_proj_kernel(
    const float* __restrict__ emb_node,
    const float* __restrict__ W_node, const float* __restrict__ b_node,
    const float* __restrict__ W_nodes, const float* __restrict__ b_nodes,
    const float* __restrict__ W_edge)
{
    __shared__ float wsm0[KN * FF];
    __shared__ float wsm1[KN * FF];
    __shared__ float rsm[8 * KN];

    const int tid = threadIdx.x;
    const int row0 = blockIdx.x * 8;

    if (blockIdx.x == 0) {
        // B fragment packs (interleaved hi/lo)
        #pragma unroll
        for (int i = 0; i < 4; i++) {
            int idx = tid + i * 256;              // 0..1023
            int lane = idx & 31;
            int ks   = (idx >> 5) & 3;
            int nt   = idx >> 7;
            int k0 = ks * 8 + (lane & 3);
            int f  = nt * 8 + (lane >> 2);
            float v0 = W_edge[k0 * FF + f];
            float v1 = W_edge[(k0 + 4) * FF + f];
            uint32_t h0 = tf32_rna(v0), h1 = tf32_rna(v1);
            uint4 p;
            p.x = h0; p.y = h1;
            p.z = tf32_rna(v0 - __uint_as_float(h0));
            p.w = tf32_rna(v1 - __uint_as_float(h1));
            g_Bp[idx] = p;
        }
    }

    {
        const float4* w0 = (const float4*)W_node;
        const float4* w1 = (const float4*)W_nodes;
        #pragma unroll
        for (int i = tid; i < KN * FF / 4; i += 256) {
            ((float4*)wsm0)[i] = w0[i];
            ((float4*)wsm1)[i] = w1[i];
        }
        if (tid < 128)
            ((float4*)rsm)[tid] = ((const float4*)(emb_node + (size_t)row0 * KN))[tid];
    }
    __syncthreads();

    const int rl = tid >> 6;
    const int f  = tid & 63;

    float nx0 = b_node[f], sx0 = b_nodes[f];
    float nx1 = nx0,       sx1 = sx0;
    #pragma unroll
    for (int k = 0; k < KN; k++) {
        float a0 = rsm[rl * KN + k];
        float a1 = rsm[(rl + 4) * KN + k];
        float w0 = wsm0[k * FF + f];
        float w1 = wsm1[k * FF + f];
        nx0 = fmaf(a0, w0, nx0);  sx0 = fmaf(a0, w1, sx0);
        nx1 = fmaf(a1, w0, nx1);  sx1 = fmaf(a1, w1, sx1);
    }

    // scatter node_x into fragment layout (half/warp/rs indexing)
    const int nt = f >> 3;
    const int cc = (f >> 1) & 3;
    const int j  = f & 1;
    {
        const int ga = row0 + rl;
        const int bbv = ga >> 8, m = ga & 255;
        const int hf = m >> 7, wi = (m >> 4) & 7, rs = (m >> 3) & 1;
        const int lp = ((m & 7) << 2) | cc;
        g_nxF[(size_t)((((((bbv * 2 + hf) * 8 + wi) * 2 + rs) * 8 + nt) * 32 + lp) * 2 + j)] = nx0;
        g_rsx[(size_t)ga * FF + f] = fmaxf(sx0, 0.0f);
    }
    {
        const int gb = row0 + rl + 4;
        const int bbv = gb >> 8, m = gb & 255;
        const int hf = m >> 7, wi = (m >> 4) & 7, rs = (m >> 3) & 1;
        const int lp = ((m & 7) << 2) | cc;
        g_nxF[(size_t)((((((bbv * 2 + hf) * 8 + wi) * 2 + rs) * 8 + nt) * 32 + lp) * 2 + j)] = nx1;
        g_rsx[(size_t)gb * FF + f] = fmaxf(sx1, 0.0f);
    }
}

// ============================================================
// Kernel 2: per (b,n,half) CTA — 128 m x 64 f x 32 k, tf32 mma.sync (3xTF32)
//   8 warps; warp w owns m-tile w (rows 16w..16w+16), all 8 n-tiles
// ============================================================
#define OFF_BES  0          // 256 B bias
#define OFF_ASM  256        // 512 B A slice (128 floats)
#define OFF_RED  768        // 2048 B (8 warps x 32 float2)
#define OFF_RAW  3328       // 18432 B raw A half-tile, rows padded to 36 floats
#define OFF_B    21760      // 16384 B interleaved B frag packs
#define EDGE_SMEM_TOTAL 38144

__global__ void __launch_bounds__(256, 3) edge_kernel(
    const float* __restrict__ A,
    const float* __restrict__ emb_edge,
    const float* __restrict__ b_edge,
    float* __restrict__ out)
{
    extern __shared__ char smem[];
    const uint32_t sb = smem_u32(smem);
    const int tid  = threadIdx.x;
    const int w    = tid >> 5;
    const int lane = tid & 31;
    const int g2   = blockIdx.x;          // (b*256+n)*2 + half
    const int g    = g2 >> 1;
    const int half = g2 & 1;
    const int b    = g >> 8;

    // ---- stage via cp.async ----
    {
        const float4* esrc =
            (const float4*)(emb_edge + ((size_t)g * NN + half * 128) * KE);
        #pragma unroll
        for (int i = 0; i < 4; i++) {
            int c = tid + i * 256;            // 0..1023 16B chunks (128 rows x 8)
            int row = c >> 3, c8 = c & 7;
            cpa16(sb + OFF_RAW + row * 144 + c8 * 16, esrc + c);
        }
        #pragma unroll
        for (int i = 0; i < 4; i++) {
            int c = tid + i * 256;            // 1024 chunks of B pack
            cpa16(sb + OFF_B + c * 16, ((const uint4*)g_Bp) + c);
        }
        if (tid < 32)
            cpa16(sb + OFF_ASM + tid * 16,
                  ((const float4*)(A + (size_t)g * NN + half * 128)) + tid);
        if (tid < 16)
            cpa16(sb + OFF_BES + tid * 16, ((const float4*)b_edge) + tid);
        cpa_commit_wait();
    }
    __syncthreads();

    const float* raw = (const float*)(smem + OFF_RAW);
    const uint4* Bsm = (const uint4*)(smem + OFF_B);

    // ---- GEMM: 1 m-tile x 8 n-tiles x 4 k-steps x 3 passes ----
    float acc[8][4];
    #pragma unroll
    for (int nt = 0; nt < 8; nt++)
        #pragma unroll
        for (int j = 0; j < 4; j++) acc[nt][j] = 0.0f;

    #pragma unroll
    for (int ks = 0; ks < 4; ks++) {
        uint32_t ah[4], al[4];
        {
            const int r0 = w * 16 + (lane >> 2);
            const int c0 = ks * 8 + (lane & 3);
            float v0 = raw[r0 * 36 + c0];
            float v1 = raw[(r0 + 8) * 36 + c0];
            float v2 = raw[r0 * 36 + c0 + 4];
            float v3 = raw[(r0 + 8) * 36 + c0 + 4];
            ah[0] = tf32_rna(v0); ah[1] = tf32_rna(v1);
            ah[2] = tf32_rna(v2); ah[3] = tf32_rna(v3);
            al[0] = tf32_rna(v0 - __uint_as_float(ah[0]));
            al[1] = tf32_rna(v1 - __uint_as_float(ah[1]));
            al[2] = tf32_rna(v2 - __uint_as_float(ah[2]));
            al[3] = tf32_rna(v3 - __uint_as_float(ah[3]));
        }
        #pragma unroll
        for (int nt = 0; nt < 8; nt++) {
            uint4 Bv = Bsm[(nt * 4 + ks) * 32 + lane];
            uint32_t bh[2] = {Bv.x, Bv.y};
            uint32_t bl[2] = {Bv.z, Bv.w};
            mma_tf32(acc[nt], ah, bh);
            mma_tf32(acc[nt], al, bh);
            mma_tf32(acc[nt], ah, bl);
        }
    }

    // ---- epilogue ----
    const float* Asmf = (const float*)(smem + OFF_ASM);
    const float* bes  = (const float*)(smem + OFF_BES);
    float* eout = out + NODE_OUT_ELEMS + (size_t)g * (NN * FF);
    const float2* nxw = ((const float2*)g_nxF) + ((size_t)((b * 2 + half) * 8 + w)) * 512;

    u64 part[8];
    #pragma unroll
    for (int nt = 0; nt < 8; nt++) part[nt] = 0ull;

    #pragma unroll
    for (int rs = 0; rs < 2; rs++) {
        const int ml = w * 16 + rs * 8 + (lane >> 2);   // local row
        const int m  = half * 128 + ml;                 // global row
        const float Am = Asmf[ml];
        const u64 A2 = pack2(Am, Am);
        #pragma unroll
        for (int nt = 0; nt < 8; nt++) {
            const int fo = nt * 8 + 2 * (lane & 3);
            float ex = acc[nt][rs * 2 + 0] + bes[fo];
            float ey = acc[nt][rs * 2 + 1] + bes[fo + 1];
            stg_cs_f2(&eout[(size_t)m * FF + fo], fmaxf(ex, 0.f), fmaxf(ey, 0.f));
            float2 nx = __ldg(&nxw[(rs * 8 + nt) * 32 + lane]);
            part[nt] = ffma2(fmul2(A2, pack2(nx.x, nx.y)), pack2(ex, ey), part[nt]);
        }
    }

    // reduce over the 8 row-slots in the warp (bits of lane>>2)
    #pragma unroll
    for (int d = 4; d <= 16; d <<= 1) {
        #pragma unroll
        for (int nt = 0; nt < 8; nt++)
            part[nt] = fadd2(part[nt], __shfl_xor_sync(0xffffffffu, part[nt], d));
    }
    if (lane < 4) {
        float2* red = (float2*)(smem + OFF_RED);
        #pragma unroll
        for (int nt = 0; nt < 8; nt++)
            red[w * 32 + nt * 4 + lane] = unpack2(part[nt]);
    }
    __syncthreads();

    // combine 8 warps (this half's 128 rows) -> g_part
    if (tid < 32) {
        const float2* red = (const float2*)(smem + OFF_RED);
        float2 s = red[tid];
        #pragma unroll
        for (int q = 1; q < 8; q++) {
            float2 v = red[q * 32 + tid];
            s.x += v.x; s.y += v.y;
        }
        g_part[(size_t)g2 * 32 + tid] = s;
    }
}

// ============================================================
// Kernel 3: combine halves -> node_out = relu(p0+p1) + rsx
// ============================================================
__global__ void __launch_bounds__(256) finish_kernel(float* __restrict__ out)
{
    const int idx = blockIdx.x * 256 + threadIdx.x;   // 0..65535
    const int g  = idx >> 5;
    const int fp = idx & 31;
    float2 a = g_part[(size_t)(2 * g) * 32 + fp];
    float2 b = g_part[(size_t)(2 * g + 1) * 32 + fp];
    float2 r = *(const float2*)&g_rsx[(size_t)g * FF + 2 * fp];
    float2 o;
    o.x = fmaxf(a.x + b.x, 0.0f) + r.x;
    o.y = fmaxf(a.y + b.y, 0.0f) + r.y;
    *(float2*)&out[(size_t)g * FF + 2 * fp] = o;
}

// ============================================================
// launch
// ============================================================
extern "C" void kernel_launch(void* const* d_in, const int* in_sizes, int n_in,
                              void* d_out, int out_size)
{
    const float* A        = (const float*)d_in[0];
    const float* emb_node = (const float*)d_in[1];
    const float* emb_edge = (const float*)d_in[2];
    const float* W_node   = (const float*)d_in[3];
    const float* b_node   = (const float*)d_in[4];
    const float* W_nodes  = (const float*)d_in[5];
    const float* b_nodes  = (const float*)d_in[6];
    const float* W_edge   = (const float*)d_in[7];
    const float* b_edge   = (const float*)d_in[8];
    float* out = (float*)d_out;

    static int attr_set = 0;
    if (!attr_set) {
        cudaFuncSetAttribute(edge_kernel,
                             cudaFuncAttributeMaxDynamicSharedMemorySize, EDGE_SMEM_TOTAL);
        attr_set = 1;
    }

    node_proj_kernel<<<256, 256>>>(emb_node, W_node, b_node, W_nodes, b_nodes, W_edge);
    edge_kernel<<<2 * BB * NN, 256, EDGE_SMEM_TOTAL>>>(A, emb_edge, b_edge, out);
    finish_kernel<<<256, 256>>>(out);
}